// round 7
// baseline (speedup 1.0000x reference)
#include <cuda_runtime.h>
#include <cstdint>

#define BB     256
#define II     1024
#define PP     128
#define HH     128
#define LPROT  1024

// smem (floats):
//  [0, 2048)       ent: 1024 x float2 {gate, (il | ip<<16)}
//  [2048, 2560)    wlist: 8 consumer warps x 256 bytes
//  [2560, 18944)   acc: 128 x 128 f32
static const int WL_OFF  = 2048;
static const int ACC_OFF = 2560;
static const int SMEM_F  = ACC_OFF + 128 * HH;   // 18944
static const int SMEM_B  = SMEM_F * 4;           // 75776 bytes

__device__ __forceinline__ void bar_arrive(int id) {
    asm volatile("bar.arrive %0, %1;" :: "r"(id), "r"(512) : "memory");
}
__device__ __forceinline__ void bar_sync_id(int id) {
    asm volatile("bar.sync %0, %1;" :: "r"(id), "r"(512) : "memory");
}

__global__ __launch_bounds__(512, 2)
void ile_kernel(const float* __restrict__ param_enc,
                const float* __restrict__ h_prot,
                const float* __restrict__ w1,
                const float* __restrict__ b1,
                const int*   __restrict__ idx_lig,
                const int*   __restrict__ idx_prot,
                const int*   __restrict__ protein_idx,
                const int*   __restrict__ lig_offsets,
                float*       __restrict__ out)
{
    extern __shared__ float sm[];
    float2*        ent   = reinterpret_cast<float2*>(sm);
    unsigned char* wlist = reinterpret_cast<unsigned char*>(sm + WL_OFF);
    float*         acc   = sm + ACC_OFF;

    const int b    = blockIdx.x;
    const int tid  = threadIdx.x;
    const int wid  = tid >> 5;      // 0..15
    const int lane = tid & 31;

    const float* pe   = param_enc + (size_t)b * II * PP;

    if (wid < 8) {
        // =================================================================
        // PRODUCERS (warps 0..7): stream gates for all 1024 rows.
        // Row layout: row(g) = 32*g + 4*p + rsub,  g = 0..31.
        // Block blk = rows [256*blk, 256*blk+256) = g in [8*blk, 8*blk+8).
        // After finishing a block: bar.arrive (non-blocking).
        // =================================================================
        const int p    = wid;
        const int e8   = lane & 7;
        const int rsub = lane >> 3;

        const float bias = b1[0];
        float4 wreg[4];
        #pragma unroll
        for (int k = 0; k < 4; k++)
            wreg[k] = *reinterpret_cast<const float4*>(w1 + 4 * e8 + 32 * k);

        const float* pr0 = pe + (size_t)(4 * p + rsub) * PP + 4 * e8;
        const int gstep = 32 * PP;   // 32 rows per g-step

        float4 bufA[4], bufB[4];
        #pragma unroll
        for (int k = 0; k < 4; k++)
            bufA[k] = __ldcs(reinterpret_cast<const float4*>(pr0 + 32 * k));

        for (int blk = 0; blk < 4; blk++) {
            #pragma unroll
            for (int it = 0; it < 8; it++) {
                const int g = blk * 8 + it;
                float4* cur = (g & 1) ? bufB : bufA;
                float4* nxt = (g & 1) ? bufA : bufB;
                if (g < 31) {
                    const float* pn = pr0 + (size_t)(g + 1) * gstep;
                    #pragma unroll
                    for (int k = 0; k < 4; k++)
                        nxt[k] = __ldcs(reinterpret_cast<const float4*>(pn + 32 * k));
                }
                float p0 = cur[0].x * wreg[0].x + cur[0].y * wreg[0].y
                         + cur[0].z * wreg[0].z + cur[0].w * wreg[0].w;
                float p1 = cur[1].x * wreg[1].x + cur[1].y * wreg[1].y
                         + cur[1].z * wreg[1].z + cur[1].w * wreg[1].w;
                float p2 = cur[2].x * wreg[2].x + cur[2].y * wreg[2].y
                         + cur[2].z * wreg[2].z + cur[2].w * wreg[2].w;
                float p3 = cur[3].x * wreg[3].x + cur[3].y * wreg[3].y
                         + cur[3].z * wreg[3].z + cur[3].w * wreg[3].w;
                float s = (p0 + p1) + (p2 + p3);
                s += __shfl_xor_sync(0xffffffffu, s, 1);
                s += __shfl_xor_sync(0xffffffffu, s, 2);
                s += __shfl_xor_sync(0xffffffffu, s, 4);
                if (e8 == 0) {
                    const int row = 32 * g + 4 * p + rsub;
                    ent[row].x = s + bias;
                }
            }
            bar_arrive(1 + blk);     // block's gates committed; keep streaming
        }
    } else {
        // =================================================================
        // CONSUMERS (warps 8..15): zero acc + pack indices, then per block:
        // wait, compact my il-group (il>>4 == c), gather MLP 8, smem acc.
        // =================================================================
        const int c   = wid - 8;     // 0..7, owns output rows [16c, 16c+16)
        const int ct  = tid - 256;   // 0..255

        // zero acc (16384 floats / 256 threads = 16 float4 each)
        {
            float4 z = make_float4(0.f, 0.f, 0.f, 0.f);
            float4* a4 = reinterpret_cast<float4*>(acc);
            #pragma unroll
            for (int k = 0; k < 16; k++)
                a4[ct + 256 * k] = z;
        }
        // pack (il | ip<<16) into ent[].y, coalesced
        {
            const int* il_b = idx_lig  + b * II;
            const int* ip_b = idx_prot + b * II;
            #pragma unroll
            for (int k = 0; k < 4; k++) {
                const int row = ct + 256 * k;
                ent[row].y = __uint_as_float((unsigned)il_b[row]
                                           | ((unsigned)ip_b[row] << 16));
            }
        }

        const int pb = protein_idx[b];
        const float* hp = h_prot + (size_t)pb * LPROT * HH + 4 * lane;
        unsigned char* wl = wlist + c * 256;

        for (int blk = 0; blk < 4; blk++) {
            bar_sync_id(1 + blk);    // producers' ent.x for this block ready
                                     // (also fences consumers' own init writes)
            const int j0b = blk * 256;
            // compact survivors of my group (deterministic order)
            int cnt = 0;
            #pragma unroll
            for (int j0 = 0; j0 < 256; j0 += 32) {
                float2 e = ent[j0b + j0 + lane];
                unsigned ix = __float_as_uint(e.y);
                bool mine = (e.x > 0.f) && (((ix & 0x7fu) >> 4) == (unsigned)c);
                unsigned bal = __ballot_sync(0xffffffffu, mine);
                int pos = cnt + __popc(bal & ((1u << lane) - 1u));
                if (mine) wl[pos] = (unsigned char)(j0 + lane);
                cnt += __popc(bal);
            }
            // gather + smem accumulate, 8 loads in flight
            for (int i = 0; i < cnt; i += 8) {
                float    gq[8];
                unsigned ilp = 0;
                float4   hq[8];
                #pragma unroll
                for (int q = 0; q < 8; q++) {
                    const bool v = (i + q) < cnt;
                    const int jj = j0b + (int)wl[v ? (i + q) : i];
                    float2 e = ent[jj];
                    unsigned ix = __float_as_uint(e.y);
                    gq[q] = v ? e.x : 0.f;
                    ilp |= (ix & 15u) << (4 * q);     // il low nibble
                    hq[q] = *reinterpret_cast<const float4*>(hp + (size_t)(ix >> 16) * HH);
                }
                #pragma unroll
                for (int q = 0; q < 8; q++) {
                    const float g = gq[q];
                    const int il = 16 * c + (int)((ilp >> (4 * q)) & 15u);
                    float4* ap = reinterpret_cast<float4*>(acc + il * HH + 4 * lane);
                    float4 a = *ap;                  // conflict-free: same row
                    a.x += g * hq[q].x;  a.y += g * hq[q].y;
                    a.z += g * hq[q].z;  a.w += g * hq[q].w;
                    *ap = a;
                }
            }
        }
    }

    __syncthreads();    // all gathers accumulated

    // ---- writeout: all 512 threads, coalesced float4 streaming stores ----
    {
        const int off = lig_offsets[b];
        float4*       o4 = reinterpret_cast<float4*>(out + (size_t)off * HH);
        const float4* a4 = reinterpret_cast<const float4*>(acc);
        #pragma unroll
        for (int k = 0; k < 8; k++)
            __stcs(&o4[tid + 512 * k], a4[tid + 512 * k]);
    }
}

extern "C" void kernel_launch(void* const* d_in, const int* in_sizes, int n_in,
                              void* d_out, int out_size)
{
    (void)in_sizes; (void)n_in; (void)out_size;

    cudaFuncSetAttribute(ile_kernel,
                         cudaFuncAttributeMaxDynamicSharedMemorySize, SMEM_B);

    ile_kernel<<<BB, 512, SMEM_B>>>(
        (const float*)d_in[0], (const float*)d_in[1],
        (const float*)d_in[2], (const float*)d_in[3],
        (const int*)d_in[4],   (const int*)d_in[5],
        (const int*)d_in[6],   (const int*)d_in[7],
        (float*)d_out);
}

// round 8
// speedup vs baseline: 1.4568x; 1.4568x over previous
#include <cuda_runtime.h>
#include <cstdint>

#define BB     256
#define II     1024
#define PP     128
#define HH     128
#define LPROT  1024

// smem (floats):
//  [0, 2048)       ent: 1024 x float2 {gate, (il | ip<<16)}
//  [2048, 3072)    wlist: 16 warps x 256 bytes
//  [3072, 19456)   acc: 128 x 128 f32
static const int WL_OFF  = 2048;
static const int ACC_OFF = 3072;
static const int SMEM_F  = ACC_OFF + 128 * HH;   // 19456
static const int SMEM_B  = SMEM_F * 4;           // 77824 bytes

__global__ __launch_bounds__(512, 2)
void ile_kernel(const float* __restrict__ param_enc,
                const float* __restrict__ h_prot,
                const float* __restrict__ w1,
                const float* __restrict__ b1,
                const int*   __restrict__ idx_lig,
                const int*   __restrict__ idx_prot,
                const int*   __restrict__ protein_idx,
                const int*   __restrict__ lig_offsets,
                float*       __restrict__ out)
{
    extern __shared__ float sm[];
    float2*        ent   = reinterpret_cast<float2*>(sm);
    unsigned char* wlist = reinterpret_cast<unsigned char*>(sm + WL_OFF);
    float*         acc   = sm + ACC_OFF;

    const int b    = blockIdx.x;
    const int tid  = threadIdx.x;
    const int wid  = tid >> 5;      // 0..15
    const int lane = tid & 31;
    const int e8   = lane & 7;      // column-eighth   (streaming)
    const int rsub = lane >> 3;     // row-within-warp (streaming)

    const float* pe   = param_enc + (size_t)b * II * PP;

    // ---- init: zero acc + pack (il | ip<<16), all threads, coalesced ----
    {
        float4 z = make_float4(0.f, 0.f, 0.f, 0.f);
        float4* a4 = reinterpret_cast<float4*>(acc);
        #pragma unroll
        for (int k = 0; k < 8; k++)
            a4[tid + 512 * k] = z;

        const int* il_b = idx_lig  + b * II;
        const int* ip_b = idx_prot + b * II;
        #pragma unroll
        for (int k = 0; k < 2; k++) {
            const int row = tid + 512 * k;
            ent[row].y = __uint_as_float((unsigned)il_b[row]
                                       | ((unsigned)ip_b[row] << 16));
        }
    }

    const float bias = b1[0];
    float4 wreg[4];
    #pragma unroll
    for (int k = 0; k < 4; k++)
        wreg[k] = *reinterpret_cast<const float4*>(w1 + 4 * e8 + 32 * k);

    const int pb = protein_idx[b];
    const float* hp = h_prot + (size_t)pb * LPROT * HH + 4 * lane;
    unsigned char* wl = wlist + wid * 256;

    // streaming geometry: t = 0..15, row(t) = 64*t + 4*wid + rsub
    const float* pr0 = pe + (size_t)(4 * wid + rsub) * PP + 4 * e8;
    const int tstep = 64 * PP;

    // prefetch t=0
    float4 pf[4];
    #pragma unroll
    for (int k = 0; k < 4; k++)
        pf[k] = __ldcs(reinterpret_cast<const float4*>(pr0 + 32 * k));

    // =====================================================================
    // Fused loop: 4 blocks of 256 rows. Stream gates (4 t-iters), prefetch
    // next block's first t-iter, barrier, compact, gather (MLP 4) into smem
    // acc while the prefetch loads are outstanding.
    // =====================================================================
    #pragma unroll
    for (int blk = 0; blk < 4; blk++) {
        // ---- stream this block's gates ----
        #pragma unroll
        for (int tt = 0; tt < 4; tt++) {
            const int t = blk * 4 + tt;
            float4 v[4];
            if (tt == 0) {
                v[0] = pf[0]; v[1] = pf[1]; v[2] = pf[2]; v[3] = pf[3];
            } else {
                const float* pc = pr0 + (size_t)t * tstep;
                #pragma unroll
                for (int k = 0; k < 4; k++)
                    v[k] = __ldcs(reinterpret_cast<const float4*>(pc + 32 * k));
            }
            float p0 = v[0].x * wreg[0].x + v[0].y * wreg[0].y
                     + v[0].z * wreg[0].z + v[0].w * wreg[0].w;
            float p1 = v[1].x * wreg[1].x + v[1].y * wreg[1].y
                     + v[1].z * wreg[1].z + v[1].w * wreg[1].w;
            float p2 = v[2].x * wreg[2].x + v[2].y * wreg[2].y
                     + v[2].z * wreg[2].z + v[2].w * wreg[2].w;
            float p3 = v[3].x * wreg[3].x + v[3].y * wreg[3].y
                     + v[3].z * wreg[3].z + v[3].w * wreg[3].w;
            float s = (p0 + p1) + (p2 + p3);
            s += __shfl_xor_sync(0xffffffffu, s, 1);
            s += __shfl_xor_sync(0xffffffffu, s, 2);
            s += __shfl_xor_sync(0xffffffffu, s, 4);
            if (e8 == 0) {
                const int row = 64 * t + 4 * wid + rsub;
                ent[row].x = s + bias;
            }
        }

        // ---- prefetch next block's first t-iter (in flight through gather) ----
        if (blk < 3) {
            const float* pn = pr0 + (size_t)(blk * 4 + 4) * tstep;
            #pragma unroll
            for (int k = 0; k < 4; k++)
                pf[k] = __ldcs(reinterpret_cast<const float4*>(pn + 32 * k));
        }

        __syncthreads();    // block's gates visible (and init, for blk 0)

        // ---- compact this block's survivors for my il-group ----
        const int j0b = blk * 256;
        int cnt = 0;
        #pragma unroll
        for (int j0 = 0; j0 < 256; j0 += 32) {
            float2 e = ent[j0b + j0 + lane];
            unsigned ix = __float_as_uint(e.y);
            bool mine = (e.x > 0.f) && (((ix & 0xffffu) >> 3) == (unsigned)wid);
            unsigned bal = __ballot_sync(0xffffffffu, mine);
            int pos = cnt + __popc(bal & ((1u << lane) - 1u));
            if (mine) wl[pos] = (unsigned char)(j0 + lane);
            cnt += __popc(bal);
        }

        // ---- gather + smem accumulate, 4 loads in flight ----
        for (int i = 0; i < cnt; i += 4) {
            float    gq[4];
            unsigned ilp = 0;
            float4   hq[4];
            #pragma unroll
            for (int q = 0; q < 4; q++) {
                const bool v = (i + q) < cnt;
                const int jj = j0b + (int)wl[v ? (i + q) : i];
                float2 e = ent[jj];
                unsigned ix = __float_as_uint(e.y);
                gq[q] = v ? e.x : 0.f;
                ilp |= (ix & 7u) << (8 * q);
                hq[q] = *reinterpret_cast<const float4*>(hp + (size_t)(ix >> 16) * HH);
            }
            #pragma unroll
            for (int q = 0; q < 4; q++) {
                const float g = gq[q];
                const int il = 8 * wid + (int)((ilp >> (8 * q)) & 7u);
                float4* ap = reinterpret_cast<float4*>(acc + il * HH + 4 * lane);
                float4 a = *ap;                 // same row per warp: conflict-free
                a.x += g * hq[q].x;  a.y += g * hq[q].y;
                a.z += g * hq[q].z;  a.w += g * hq[q].w;
                *ap = a;
            }
        }
        // no trailing barrier: next block reads disjoint ent rows; acc rows
        // and wlist are warp-private.
    }

    __syncthreads();    // all accumulation done

    // ---- writeout: all 512 threads, coalesced float4 streaming stores ----
    {
        const int off = lig_offsets[b];
        float4*       o4 = reinterpret_cast<float4*>(out + (size_t)off * HH);
        const float4* a4 = reinterpret_cast<const float4*>(acc);
        #pragma unroll
        for (int k = 0; k < 8; k++)
            __stcs(&o4[tid + 512 * k], a4[tid + 512 * k]);
    }
}

extern "C" void kernel_launch(void* const* d_in, const int* in_sizes, int n_in,
                              void* d_out, int out_size)
{
    (void)in_sizes; (void)n_in; (void)out_size;

    cudaFuncSetAttribute(ile_kernel,
                         cudaFuncAttributeMaxDynamicSharedMemorySize, SMEM_B);

    ile_kernel<<<BB, 512, SMEM_B>>>(
        (const float*)d_in[0], (const float*)d_in[1],
        (const float*)d_in[2], (const float*)d_in[3],
        (const int*)d_in[4],   (const int*)d_in[5],
        (const int*)d_in[6],   (const int*)d_in[7],
        (float*)d_out);
}